// round 14
// baseline (speedup 1.0000x reference)
#include <cuda_runtime.h>
#include <cuda_fp16.h>
#include <cstdint>

// GCN 2-layer, CSR-gather + tf32 tensor-core GEMMs + fp16 gather tensors.
//   dinv[i] = rsqrt(1 + indeg[i])
//   L1: raw1 = x@W1 [fp16, unscaled];  h = relu(dinv*(dinv[i]*raw1[i] + sum dinv[s]*raw1[s]) + b1)
//   L2: g2 = dinv*(h@W2) [fp16];       out = dinv*(g2[i]+sum g2[src]) + b2
// gemm1 is independent of the CSR chain (dinv deferred to agg1), so gemm1 and
// CSR-fill are FUSED into one kernel (block-range dispatch) for chip-level overlap.

#define D_IN  128
#define D_HID 128
#define D_OUT 64
#define NMAX  100000
#define EMAX  1600000
#define SCAN_BLK 1024
#define NBLK_MAX 128

// ---- scratch ----
__device__ __align__(16) float g_dinv[NMAX];
__device__ int   g_is64;
__device__ int   g_count[NMAX];
__device__ int   g_rowstart[NMAX + 1];
__device__ int   g_cursor[NMAX];
__device__ volatile unsigned long long g_blkpack[NBLK_MAX];  // (aggregate<<32)|1
__device__ int   g_srcidx[EMAX];
__device__ __align__(16) __half g_g1h[(size_t)NMAX * D_HID];  // fp16 raw x@W1 (unscaled)
__device__ __align__(16) __half g_h1h[(size_t)NMAX * D_HID];  // fp16 hidden activations
__device__ __align__(16) __half g_g2h[(size_t)NMAX * D_OUT];  // fp16 gather tensor L2

// ---------------- tf32 helpers ----------------
__device__ __forceinline__ uint32_t f2tf32(float f) {
    uint32_t u;
    asm("cvt.rna.tf32.f32 %0, %1;" : "=r"(u) : "f"(f));
    return u;
}

__device__ __forceinline__ void mma_tf32(float* d, const uint32_t* a, const uint32_t* b) {
    asm volatile(
        "mma.sync.aligned.m16n8k8.row.col.f32.tf32.tf32.f32 "
        "{%0,%1,%2,%3},{%4,%5,%6,%7},{%8,%9},{%0,%1,%2,%3};"
        : "+f"(d[0]), "+f"(d[1]), "+f"(d[2]), "+f"(d[3])
        : "r"(a[0]), "r"(a[1]), "r"(a[2]), "r"(a[3]), "r"(b[0]), "r"(b[1]));
}

// fp16x8 FMA-accumulate (scaled by s) into fp32x8
__device__ __forceinline__ void acc_u4_s(float* a, uint4 r, float s) {
    float2 t;
    t = __half22float2(*(__half2*)&r.x); a[0] = fmaf(s, t.x, a[0]); a[1] = fmaf(s, t.y, a[1]);
    t = __half22float2(*(__half2*)&r.y); a[2] = fmaf(s, t.x, a[2]); a[3] = fmaf(s, t.y, a[3]);
    t = __half22float2(*(__half2*)&r.z); a[4] = fmaf(s, t.x, a[4]); a[5] = fmaf(s, t.y, a[5]);
    t = __half22float2(*(__half2*)&r.w); a[6] = fmaf(s, t.x, a[6]); a[7] = fmaf(s, t.y, a[7]);
}

// fp16x8 accumulate into fp32x8
__device__ __forceinline__ void acc_u4(float* a, uint4 r) {
    float2 t;
    t = __half22float2(*(__half2*)&r.x); a[0] += t.x; a[1] += t.y;
    t = __half22float2(*(__half2*)&r.y); a[2] += t.x; a[3] += t.y;
    t = __half22float2(*(__half2*)&r.z); a[4] += t.x; a[5] += t.y;
    t = __half22float2(*(__half2*)&r.w); a[6] += t.x; a[7] += t.y;
}

// ---------------- zero counts/flags + edge dtype detection (fused) ----------------
__global__ void k_zero_detect(const int* __restrict__ w, long long words32, int n) {
    int i = blockIdx.x * blockDim.x + threadIdx.x;
    if (i < n) g_count[i] = 0;
    if (i < NBLK_MAX) g_blkpack[i] = 0ull;
    if (blockIdx.x == 0) {
        __shared__ int nzflag;
        if (threadIdx.x == 0) nzflag = 0;
        __syncthreads();
        long long limit = words32 < 8192 ? words32 : 8192;
        for (long long k = 1 + 2 * (long long)threadIdx.x; k < limit; k += 2 * blockDim.x)
            if (w[k] != 0) nzflag = 1;   // benign race
        __syncthreads();
        if (threadIdx.x == 0) g_is64 = (nzflag == 0) ? 1 : 0;
    }
}

// ---------------- CSR build: count (4 edges/thread, vectorized) ----------------
__global__ void k_count(const void* __restrict__ ei, long long E, int n) {
    long long q = (long long)blockIdx.x * blockDim.x + threadIdx.x;  // quad index
    long long e0 = q * 4;
    if (e0 >= E) return;
    int d[4];
    int cnt = (int)((E - e0) < 4 ? (E - e0) : 4);
    if (g_is64) {
        if (cnt == 4) {
            const longlong2* p = (const longlong2*)((const long long*)ei + E + e0);
            longlong2 a = p[0], b = p[1];
            d[0] = (int)a.x; d[1] = (int)a.y; d[2] = (int)b.x; d[3] = (int)b.y;
        } else {
            const long long* s = (const long long*)ei + E + e0;
            for (int k = 0; k < cnt; k++) d[k] = (int)s[k];
        }
    } else {
        if (cnt == 4) {
            int4 a = *(const int4*)((const int*)ei + E + e0);
            d[0] = a.x; d[1] = a.y; d[2] = a.z; d[3] = a.w;
        } else {
            const int* s = (const int*)ei + E + e0;
            for (int k = 0; k < cnt; k++) d[k] = s[k];
        }
    }
    for (int k = 0; k < cnt; k++) {
        int dst = min(max(d[k], 0), n - 1);
        atomicAdd(&g_count[dst], 1);
    }
}

// ---------------- single-kernel scan: decoupled lookback ----------------
__global__ void k_scan(int n) {
    __shared__ int sm[SCAN_BLK];
    __shared__ int s_prev;
    const int b = blockIdx.x;
    const int tid = threadIdx.x;
    const int gid = b * SCAN_BLK + tid;
    const int n1 = n + 1;

    int v = (gid < n) ? g_count[gid] : 0;
    sm[tid] = v;
    __syncthreads();
    for (int off = 1; off < SCAN_BLK; off <<= 1) {
        int t = (tid >= off) ? sm[tid - off] : 0;
        __syncthreads();
        sm[tid] += t;
        __syncthreads();
    }
    int incl = sm[tid];

    if (tid == SCAN_BLK - 1) {
        unsigned long long pack = ((unsigned long long)(unsigned)incl << 32) | 1ull;
        g_blkpack[b] = pack;
    }

    if (tid == 0) s_prev = 0;
    __syncthreads();
    int part = 0;
    for (int j = tid; j < b; j += SCAN_BLK) {
        unsigned long long w;
        do { w = g_blkpack[j]; } while (w == 0ull);
        part += (int)(w >> 32);
    }
    if (part) atomicAdd(&s_prev, part);
    __syncthreads();
    int prev = s_prev;

    int excl = prev + incl - v;
    if (gid < n1) g_rowstart[gid] = excl;
    if (gid < n) {
        g_cursor[gid] = excl;
        g_dinv[gid] = rsqrtf((float)v + 1.0f);  // +1 self-loop
    }
}

// ---------------- FUSED: gemm1 (raw x@W1 -> fp16) || CSR fill ----------------
// Blocks [0, gemmBlocks): tf32 GEMM, BM=128 BN=128, 8 warps, warp tile m64 n32.
// Blocks [gemmBlocks, ...): fill, 4 edges/thread.
#define AS_STRIDE 36
#define BS1_STRIDE 132

__global__ void k_gemm1_fill(const float* __restrict__ x, const float* __restrict__ W,
                             const void* __restrict__ ei, long long E, int n,
                             int gemmBlocks) {
    __shared__ uint32_t As[128 * AS_STRIDE];
    __shared__ uint32_t Bs[32 * BS1_STRIDE];

    if (blockIdx.x >= gemmBlocks) {
        // ---- fill branch ----
        long long q = (long long)(blockIdx.x - gemmBlocks) * blockDim.x + threadIdx.x;
        long long e0 = q * 4;
        if (e0 >= E) return;
        int s[4], d[4];
        int cnt = (int)((E - e0) < 4 ? (E - e0) : 4);
        if (g_is64) {
            if (cnt == 4) {
                const longlong2* ps = (const longlong2*)((const long long*)ei + e0);
                const longlong2* pd = (const longlong2*)((const long long*)ei + E + e0);
                longlong2 a = ps[0], b = ps[1], c = pd[0], f = pd[1];
                s[0] = (int)a.x; s[1] = (int)a.y; s[2] = (int)b.x; s[3] = (int)b.y;
                d[0] = (int)c.x; d[1] = (int)c.y; d[2] = (int)f.x; d[3] = (int)f.y;
            } else {
                const long long* ps = (const long long*)ei + e0;
                const long long* pd = (const long long*)ei + E + e0;
                for (int k = 0; k < cnt; k++) { s[k] = (int)ps[k]; d[k] = (int)pd[k]; }
            }
        } else {
            if (cnt == 4) {
                int4 a = *(const int4*)((const int*)ei + e0);
                int4 c = *(const int4*)((const int*)ei + E + e0);
                s[0] = a.x; s[1] = a.y; s[2] = a.z; s[3] = a.w;
                d[0] = c.x; d[1] = c.y; d[2] = c.z; d[3] = c.w;
            } else {
                const int* ps = (const int*)ei + e0;
                const int* pd = (const int*)ei + E + e0;
                for (int k = 0; k < cnt; k++) { s[k] = ps[k]; d[k] = pd[k]; }
            }
        }
        for (int k = 0; k < cnt; k++) {
            int src = min(max(s[k], 0), n - 1);
            int dst = min(max(d[k], 0), n - 1);
            int pos = atomicAdd(&g_cursor[dst], 1);
            pos = min(max(pos, 0), EMAX - 1);
            g_srcidx[pos] = src;
        }
        return;
    }

    // ---- gemm branch ----
    const int t = threadIdx.x;
    const int wid = t >> 5, lane = t & 31;
    const int wm = wid & 1, wn = wid >> 1;
    const int m0 = blockIdx.x * 128;

    float acc[4][4][4];
#pragma unroll
    for (int mt = 0; mt < 4; mt++)
#pragma unroll
        for (int nt = 0; nt < 4; nt++)
#pragma unroll
            for (int r = 0; r < 4; r++) acc[mt][nt][r] = 0.0f;

    for (int kc = 0; kc < 128; kc += 32) {
        for (int i = t; i < 1024; i += 256) {
            int m = i >> 3, k4 = (i & 7) * 4;
            int row = m0 + m;
            float4 v = make_float4(0.f, 0.f, 0.f, 0.f);
            if (row < n) v = *(const float4*)&x[(size_t)row * D_IN + kc + k4];
            uint32_t* p = &As[m * AS_STRIDE + k4];
            p[0] = f2tf32(v.x); p[1] = f2tf32(v.y); p[2] = f2tf32(v.z); p[3] = f2tf32(v.w);
        }
        for (int i = t; i < 1024; i += 256) {
            int k = i >> 5, n4 = (i & 31) * 4;
            float4 v = *(const float4*)&W[(size_t)(kc + k) * D_HID + n4];
            uint32_t* p = &Bs[k * BS1_STRIDE + n4];
            p[0] = f2tf32(v.x); p[1] = f2tf32(v.y); p[2] = f2tf32(v.z); p[3] = f2tf32(v.w);
        }
        __syncthreads();

#pragma unroll
        for (int ks = 0; ks < 4; ks++) {
            const int kb = ks * 8;
            uint32_t a[4][4], b[4][2];
            const int ar = wm * 64 + (lane >> 2);
            const int ac = kb + (lane & 3);
#pragma unroll
            for (int mt = 0; mt < 4; mt++) {
                a[mt][0] = As[(ar + mt * 16)     * AS_STRIDE + ac];
                a[mt][1] = As[(ar + mt * 16 + 8) * AS_STRIDE + ac];
                a[mt][2] = As[(ar + mt * 16)     * AS_STRIDE + ac + 4];
                a[mt][3] = As[(ar + mt * 16 + 8) * AS_STRIDE + ac + 4];
            }
            const int bn = wn * 32 + (lane >> 2);
            const int bk = kb + (lane & 3);
#pragma unroll
            for (int nt = 0; nt < 4; nt++) {
                b[nt][0] = Bs[bk       * BS1_STRIDE + bn + nt * 8];
                b[nt][1] = Bs[(bk + 4) * BS1_STRIDE + bn + nt * 8];
            }
#pragma unroll
            for (int mt = 0; mt < 4; mt++)
#pragma unroll
                for (int nt = 0; nt < 4; nt++) mma_tf32(acc[mt][nt], a[mt], b[nt]);
        }
        __syncthreads();
    }

    // epilogue: store RAW result (dinv deferred to agg1)
    const int rbase = m0 + wm * 64 + (lane >> 2);
    const int cbase = wn * 32 + (lane & 3) * 2;
#pragma unroll
    for (int mt = 0; mt < 4; mt++) {
#pragma unroll
        for (int half = 0; half < 2; half++) {
            int row = rbase + mt * 16 + half * 8;
            if (row < n) {
#pragma unroll
                for (int nt = 0; nt < 4; nt++) {
                    int col = cbase + nt * 8;
                    *(__half2*)&g_g1h[(size_t)row * D_HID + col] =
                        __float22half2_rn(make_float2(acc[mt][nt][2 * half],
                                                      acc[mt][nt][2 * half + 1]));
                }
            }
        }
    }
}

// ---------------- aggregation layer 1 + L2 activation (fused, deferred dinv) ----------------
// 2 nodes/warp; 16 lanes/node; lane owns uint4 (8 halfs) of 256B row.
// h = relu(dinv[i]*(dinv[i]*raw[i] + sum dinv[s]*raw[s]) + b1), fp16.
__global__ void k_agg1(const float* __restrict__ b1, int n) {
    int gw = (blockIdx.x * blockDim.x + threadIdx.x) >> 5;
    int lane = threadIdx.x & 31;
    int node = gw * 2 + (lane >> 4);
    int lane16 = lane & 15;
    if (node >= n) return;

    const uint4* base = (const uint4*)g_g1h;   // row = 16 uint4
    float dv = g_dinv[node];
    float a[8] = {0, 0, 0, 0, 0, 0, 0, 0};
    acc_u4_s(a, base[(size_t)node * 16 + lane16], dv);   // self term: dinv[i]*raw[i]

    int beg = g_rowstart[node], end = g_rowstart[node + 1];
    int j = beg;
    for (; j + 4 <= end; j += 4) {
        int s0 = g_srcidx[j], s1 = g_srcidx[j + 1], s2 = g_srcidx[j + 2], s3 = g_srcidx[j + 3];
        float v0 = g_dinv[s0], v1 = g_dinv[s1], v2 = g_dinv[s2], v3 = g_dinv[s3];
        uint4 r0 = base[(size_t)s0 * 16 + lane16];
        uint4 r1 = base[(size_t)s1 * 16 + lane16];
        uint4 r2 = base[(size_t)s2 * 16 + lane16];
        uint4 r3 = base[(size_t)s3 * 16 + lane16];
        acc_u4_s(a, r0, v0); acc_u4_s(a, r1, v1); acc_u4_s(a, r2, v2); acc_u4_s(a, r3, v3);
    }
    for (; j < end; j++) {
        int s = g_srcidx[j];
        acc_u4_s(a, base[(size_t)s * 16 + lane16], g_dinv[s]);
    }

    float4 bb0 = *(const float4*)&b1[lane16 * 8];
    float4 bb1 = *(const float4*)&b1[lane16 * 8 + 4];
    float h0 = fmaxf(fmaf(dv, a[0], bb0.x), 0.f), h1 = fmaxf(fmaf(dv, a[1], bb0.y), 0.f);
    float h2 = fmaxf(fmaf(dv, a[2], bb0.z), 0.f), h3 = fmaxf(fmaf(dv, a[3], bb0.w), 0.f);
    float h4 = fmaxf(fmaf(dv, a[4], bb1.x), 0.f), h5 = fmaxf(fmaf(dv, a[5], bb1.y), 0.f);
    float h6 = fmaxf(fmaf(dv, a[6], bb1.z), 0.f), h7 = fmaxf(fmaf(dv, a[7], bb1.w), 0.f);
    uint4 outw;
    *(__half2*)&outw.x = __float22half2_rn(make_float2(h0, h1));
    *(__half2*)&outw.y = __float22half2_rn(make_float2(h2, h3));
    *(__half2*)&outw.z = __float22half2_rn(make_float2(h4, h5));
    *(__half2*)&outw.w = __float22half2_rn(make_float2(h6, h7));
    ((uint4*)g_h1h)[(size_t)node * 16 + lane16] = outw;
}

// ---------------- GEMM layer 2 (tf32 MMA): g2h = fp16(dinv*(h @ W2)), h fp16 ----------------
#define BS2_STRIDE 68

__global__ void k_gemm2(const float* __restrict__ W, int n) {
    __shared__ uint32_t As[128 * AS_STRIDE];
    __shared__ uint32_t Bs[32 * BS2_STRIDE];

    const int t = threadIdx.x;
    const int wid = t >> 5, lane = t & 31;
    const int wm = wid & 1, wn = wid >> 1;
    const int m0 = blockIdx.x * 128;

    float acc[4][2][4];
#pragma unroll
    for (int mt = 0; mt < 4; mt++)
#pragma unroll
        for (int nt = 0; nt < 2; nt++)
#pragma unroll
            for (int r = 0; r < 4; r++) acc[mt][nt][r] = 0.0f;

    for (int kc = 0; kc < 128; kc += 32) {
        for (int i = t; i < 1024; i += 256) {
            int m = i >> 3, k4 = (i & 7) * 4;
            int row = m0 + m;
            uint32_t* p = &As[m * AS_STRIDE + k4];
            if (row < n) {
                uint2 raw = *(const uint2*)&g_h1h[(size_t)row * D_HID + kc + k4];
                float2 t0 = __half22float2(*(__half2*)&raw.x);
                float2 t1 = __half22float2(*(__half2*)&raw.y);
                p[0] = f2tf32(t0.x); p[1] = f2tf32(t0.y);
                p[2] = f2tf32(t1.x); p[3] = f2tf32(t1.y);
            } else {
                p[0] = 0u; p[1] = 0u; p[2] = 0u; p[3] = 0u;
            }
        }
        for (int i = t; i < 512; i += 256) {
            int k = i >> 4, n4 = (i & 15) * 4;
            float4 v = *(const float4*)&W[(size_t)(kc + k) * D_OUT + n4];
            uint32_t* p = &Bs[k * BS2_STRIDE + n4];
            p[0] = f2tf32(v.x); p[1] = f2tf32(v.y); p[2] = f2tf32(v.z); p[3] = f2tf32(v.w);
        }
        __syncthreads();

#pragma unroll
        for (int ks = 0; ks < 4; ks++) {
            const int kb = ks * 8;
            uint32_t a[4][4], b[2][2];
            const int ar = wm * 64 + (lane >> 2);
            const int ac = kb + (lane & 3);
#pragma unroll
            for (int mt = 0; mt < 4; mt++) {
                a[mt][0] = As[(ar + mt * 16)     * AS_STRIDE + ac];
                a[mt][1] = As[(ar + mt * 16 + 8) * AS_STRIDE + ac];
                a[mt][2] = As[(ar + mt * 16)     * AS_STRIDE + ac + 4];
                a[mt][3] = As[(ar + mt * 16 + 8) * AS_STRIDE + ac + 4];
            }
            const int bn = wn * 16 + (lane >> 2);
            const int bk = kb + (lane & 3);
#pragma unroll
            for (int nt = 0; nt < 2; nt++) {
                b[nt][0] = Bs[bk       * BS2_STRIDE + bn + nt * 8];
                b[nt][1] = Bs[(bk + 4) * BS2_STRIDE + bn + nt * 8];
            }
#pragma unroll
            for (int mt = 0; mt < 4; mt++)
#pragma unroll
                for (int nt = 0; nt < 2; nt++) mma_tf32(acc[mt][nt], a[mt], b[nt]);
        }
        __syncthreads();
    }

    const int rbase = m0 + wm * 64 + (lane >> 2);
    const int cbase = wn * 16 + (lane & 3) * 2;
#pragma unroll
    for (int mt = 0; mt < 4; mt++) {
#pragma unroll
        for (int half = 0; half < 2; half++) {
            int row = rbase + mt * 16 + half * 8;
            if (row < n) {
                float dv = g_dinv[row];
#pragma unroll
                for (int nt = 0; nt < 2; nt++) {
                    int col = cbase + nt * 8;
                    *(__half2*)&g_g2h[(size_t)row * D_OUT + col] =
                        __float22half2_rn(make_float2(dv * acc[mt][nt][2 * half],
                                                      dv * acc[mt][nt][2 * half + 1]));
                }
            }
        }
    }
}

// ---------------- aggregation layer 2 + epilogue ----------------
// 4 nodes/warp; 8 lanes/node; lane owns uint4 (8 halfs) of 128B row.
__global__ void k_agg2(const float* __restrict__ b2, float* __restrict__ out, int n) {
    int gw = (blockIdx.x * blockDim.x + threadIdx.x) >> 5;
    int lane = threadIdx.x & 31;
    int node = gw * 4 + (lane >> 3);
    int lane8 = lane & 7;
    if (node >= n) return;

    const uint4* base = (const uint4*)g_g2h;   // row = 8 uint4
    float a[8];
    {
        uint4 r = base[(size_t)node * 8 + lane8];
        float2 t;
        t = __half22float2(*(__half2*)&r.x); a[0] = t.x; a[1] = t.y;
        t = __half22float2(*(__half2*)&r.y); a[2] = t.x; a[3] = t.y;
        t = __half22float2(*(__half2*)&r.z); a[4] = t.x; a[5] = t.y;
        t = __half22float2(*(__half2*)&r.w); a[6] = t.x; a[7] = t.y;
    }

    int beg = g_rowstart[node], end = g_rowstart[node + 1];
    int j = beg;
    for (; j + 4 <= end; j += 4) {
        int s0 = g_srcidx[j], s1 = g_srcidx[j + 1], s2 = g_srcidx[j + 2], s3 = g_srcidx[j + 3];
        uint4 r0 = base[(size_t)s0 * 8 + lane8];
        uint4 r1 = base[(size_t)s1 * 8 + lane8];
        uint4 r2 = base[(size_t)s2 * 8 + lane8];
        uint4 r3 = base[(size_t)s3 * 8 + lane8];
        acc_u4(a, r0); acc_u4(a, r1); acc_u4(a, r2); acc_u4(a, r3);
    }
    for (; j < end; j++) {
        uint4 r = base[(size_t)g_srcidx[j] * 8 + lane8];
        acc_u4(a, r);
    }

    float dv = g_dinv[node];
    const float4* b24 = (const float4*)b2;
    float4 bb0 = b24[lane8 * 2], bb1 = b24[lane8 * 2 + 1];
    float4* outp = (float4*)out + (size_t)node * 16 + lane8 * 2;
    outp[0] = make_float4(fmaf(dv, a[0], bb0.x), fmaf(dv, a[1], bb0.y),
                          fmaf(dv, a[2], bb0.z), fmaf(dv, a[3], bb0.w));
    outp[1] = make_float4(fmaf(dv, a[4], bb1.x), fmaf(dv, a[5], bb1.y),
                          fmaf(dv, a[6], bb1.z), fmaf(dv, a[7], bb1.w));
}

// ---------------- launch ----------------
extern "C" void kernel_launch(void* const* d_in, const int* in_sizes, int n_in,
                              void* d_out, int out_size) {
    const float* x  = nullptr;
    const void*  ei = nullptr;
    const float* W1 = nullptr;
    const float* b1 = nullptr;
    const float* W2 = nullptr;
    const float* b2 = nullptr;
    int x_elems = 0, ei_elems = 0;

    int imax = 0, imax2 = -1;
    for (int i = 1; i < n_in; i++) if (in_sizes[i] > in_sizes[imax]) imax = i;
    for (int i = 0; i < n_in; i++) {
        if (i == imax) continue;
        if (imax2 < 0 || in_sizes[i] > in_sizes[imax2]) imax2 = i;
    }
    x  = (const float*)d_in[imax];  x_elems  = in_sizes[imax];
    ei = (const void*)d_in[imax2];  ei_elems = in_sizes[imax2];

    for (int i = 0; i < n_in; i++) {
        if (i == imax || i == imax2) continue;
        int s = in_sizes[i];
        if      (s == D_IN * D_HID)  W1 = (const float*)d_in[i];
        else if (s == D_HID)         b1 = (const float*)d_in[i];
        else if (s == D_HID * D_OUT) W2 = (const float*)d_in[i];
        else if (s == D_OUT)         b2 = (const float*)d_in[i];
    }

    float* out = (float*)d_out;
    const int n = x_elems / D_IN;
    const long long E = (long long)ei_elems / 2;
    const int n1 = n + 1;
    const int nb = (n1 + SCAN_BLK - 1) / SCAN_BLK;
    const long long Q = (E + 3) / 4;               // 4 edges per thread
    const int fillBlocks = (int)((Q + 255) / 256);
    const int gemmBlocks = (n + 127) / 128;

    // CSR count + scan (gemm1 no longer depends on these)
    k_zero_detect<<<(n + 255) / 256, 256>>>((const int*)ei, (long long)ei_elems, n);
    k_count<<<fillBlocks, 256>>>(ei, E, n);
    k_scan <<<nb, SCAN_BLK>>>(n);

    // overlap: gemm1 (raw) || CSR fill, one fused kernel
    k_gemm1_fill<<<gemmBlocks + fillBlocks, 256>>>(x, W1, ei, E, n, gemmBlocks);

    // layer 1 aggregation (+ReLU/bias, deferred dinv)
    k_agg1 <<<(n + 15) / 16, 256>>>(b1, n);        // 2 nodes/warp

    // layer 2
    k_gemm2<<<gemmBlocks, 256>>>(W2, n);
    k_agg2 <<<(n + 31) / 32, 256>>>(b2, out, n);   // 4 nodes/warp
}

// round 16
// speedup vs baseline: 1.1114x; 1.1114x over previous
#include <cuda_runtime.h>
#include <cuda_fp16.h>
#include <cstdint>

// GCN 2-layer, CSR-gather + tf32 tensor-core GEMMs (cp.async pipelined) + fp16 gather tensors.
//   dinv[i] = rsqrt(1 + indeg[i])
//   L1: raw1 = x@W1 [fp16, unscaled];  h = relu(dinv*(dinv[i]*raw1[i] + sum dinv[s]*raw1[s]) + b1)
//   L2: g2 = dinv*(h@W2) [fp16];       out = dinv*(g2[i]+sum g2[src]) + b2
// tf32 conversion uses cvt.rna (round-to-nearest) — REQUIRED for accuracy; raw-bit
// truncation measured rel_err 1.1e-3 (fail) vs 2.7e-4 with rna.

#define D_IN  128
#define D_HID 128
#define D_OUT 64
#define NMAX  100000
#define EMAX  1600000
#define SCAN_BLK 1024
#define NBLK_MAX 128

// ---- scratch ----
__device__ __align__(16) float g_dinv[NMAX];
__device__ int   g_is64;
__device__ int   g_count[NMAX];
__device__ int   g_rowstart[NMAX + 1];
__device__ int   g_cursor[NMAX];
__device__ volatile unsigned long long g_blkpack[NBLK_MAX];
__device__ int   g_srcidx[EMAX];
__device__ __align__(16) __half g_g1h[(size_t)NMAX * D_HID];  // fp16 raw x@W1
__device__ __align__(16) __half g_h1h[(size_t)NMAX * D_HID];  // fp16 hidden act
__device__ __align__(16) __half g_g2h[(size_t)NMAX * D_OUT];  // fp16 gather tensor L2

// ---------------- tf32 helpers ----------------
__device__ __forceinline__ uint32_t f2tf32(float f) {
    uint32_t u;
    asm("cvt.rna.tf32.f32 %0, %1;" : "=r"(u) : "f"(f));
    return u;
}

__device__ __forceinline__ uint32_t s2tf32(float f) {  // from smem float
    return f2tf32(f);
}

__device__ __forceinline__ void mma_tf32(float* d, const uint32_t* a, const uint32_t* b) {
    asm volatile(
        "mma.sync.aligned.m16n8k8.row.col.f32.tf32.tf32.f32 "
        "{%0,%1,%2,%3},{%4,%5,%6,%7},{%8,%9},{%0,%1,%2,%3};"
        : "+f"(d[0]), "+f"(d[1]), "+f"(d[2]), "+f"(d[3])
        : "r"(a[0]), "r"(a[1]), "r"(a[2]), "r"(a[3]), "r"(b[0]), "r"(b[1]));
}

// fp16x8 FMA-accumulate (scaled by s) into fp32x8
__device__ __forceinline__ void acc_u4_s(float* a, uint4 r, float s) {
    float2 t;
    t = __half22float2(*(__half2*)&r.x); a[0] = fmaf(s, t.x, a[0]); a[1] = fmaf(s, t.y, a[1]);
    t = __half22float2(*(__half2*)&r.y); a[2] = fmaf(s, t.x, a[2]); a[3] = fmaf(s, t.y, a[3]);
    t = __half22float2(*(__half2*)&r.z); a[4] = fmaf(s, t.x, a[4]); a[5] = fmaf(s, t.y, a[5]);
    t = __half22float2(*(__half2*)&r.w); a[6] = fmaf(s, t.x, a[6]); a[7] = fmaf(s, t.y, a[7]);
}

// fp16x8 accumulate into fp32x8
__device__ __forceinline__ void acc_u4(float* a, uint4 r) {
    float2 t;
    t = __half22float2(*(__half2*)&r.x); a[0] += t.x; a[1] += t.y;
    t = __half22float2(*(__half2*)&r.y); a[2] += t.x; a[3] += t.y;
    t = __half22float2(*(__half2*)&r.z); a[4] += t.x; a[5] += t.y;
    t = __half22float2(*(__half2*)&r.w); a[6] += t.x; a[7] += t.y;
}

// ---------------- zero + dtype detect ----------------
__global__ void k_zero_detect(const int* __restrict__ w, long long words32, int n) {
    int i = blockIdx.x * blockDim.x + threadIdx.x;
    if (i < n) g_count[i] = 0;
    if (i < NBLK_MAX) g_blkpack[i] = 0ull;
    if (blockIdx.x == 0) {
        __shared__ int nzflag;
        if (threadIdx.x == 0) nzflag = 0;
        __syncthreads();
        long long limit = words32 < 8192 ? words32 : 8192;
        for (long long k = 1 + 2 * (long long)threadIdx.x; k < limit; k += 2 * blockDim.x)
            if (w[k] != 0) nzflag = 1;
        __syncthreads();
        if (threadIdx.x == 0) g_is64 = (nzflag == 0) ? 1 : 0;
    }
}

// ---------------- count (4 edges/thread) ----------------
__global__ void k_count(const void* __restrict__ ei, long long E, int n) {
    long long q = (long long)blockIdx.x * blockDim.x + threadIdx.x;
    long long e0 = q * 4;
    if (e0 >= E) return;
    int d[4];
    int cnt = (int)((E - e0) < 4 ? (E - e0) : 4);
    if (g_is64) {
        if (cnt == 4) {
            const longlong2* p = (const longlong2*)((const long long*)ei + E + e0);
            longlong2 a = p[0], b = p[1];
            d[0] = (int)a.x; d[1] = (int)a.y; d[2] = (int)b.x; d[3] = (int)b.y;
        } else {
            const long long* s = (const long long*)ei + E + e0;
            for (int k = 0; k < cnt; k++) d[k] = (int)s[k];
        }
    } else {
        if (cnt == 4) {
            int4 a = *(const int4*)((const int*)ei + E + e0);
            d[0] = a.x; d[1] = a.y; d[2] = a.z; d[3] = a.w;
        } else {
            const int* s = (const int*)ei + E + e0;
            for (int k = 0; k < cnt; k++) d[k] = s[k];
        }
    }
    for (int k = 0; k < cnt; k++) {
        int dst = min(max(d[k], 0), n - 1);
        atomicAdd(&g_count[dst], 1);
    }
}

// ---------------- decoupled-lookback scan ----------------
__global__ void k_scan(int n) {
    __shared__ int sm[SCAN_BLK];
    __shared__ int s_prev;
    const int b = blockIdx.x;
    const int tid = threadIdx.x;
    const int gid = b * SCAN_BLK + tid;
    const int n1 = n + 1;

    int v = (gid < n) ? g_count[gid] : 0;
    sm[tid] = v;
    __syncthreads();
    for (int off = 1; off < SCAN_BLK; off <<= 1) {
        int t = (tid >= off) ? sm[tid - off] : 0;
        __syncthreads();
        sm[tid] += t;
        __syncthreads();
    }
    int incl = sm[tid];

    if (tid == SCAN_BLK - 1)
        g_blkpack[b] = ((unsigned long long)(unsigned)incl << 32) | 1ull;

    if (tid == 0) s_prev = 0;
    __syncthreads();
    int part = 0;
    for (int j = tid; j < b; j += SCAN_BLK) {
        unsigned long long w;
        do { w = g_blkpack[j]; } while (w == 0ull);
        part += (int)(w >> 32);
    }
    if (part) atomicAdd(&s_prev, part);
    __syncthreads();
    int prev = s_prev;

    int excl = prev + incl - v;
    if (gid < n1) g_rowstart[gid] = excl;
    if (gid < n) {
        g_cursor[gid] = excl;
        g_dinv[gid] = rsqrtf((float)v + 1.0f);
    }
}

// ---------------- fill (4 edges/thread) ----------------
__global__ void k_fill(const void* __restrict__ ei, long long E, int n) {
    long long q = (long long)blockIdx.x * blockDim.x + threadIdx.x;
    long long e0 = q * 4;
    if (e0 >= E) return;
    int s[4], d[4];
    int cnt = (int)((E - e0) < 4 ? (E - e0) : 4);
    if (g_is64) {
        if (cnt == 4) {
            const longlong2* ps = (const longlong2*)((const long long*)ei + e0);
            const longlong2* pd = (const longlong2*)((const long long*)ei + E + e0);
            longlong2 a = ps[0], b = ps[1], c = pd[0], f = pd[1];
            s[0] = (int)a.x; s[1] = (int)a.y; s[2] = (int)b.x; s[3] = (int)b.y;
            d[0] = (int)c.x; d[1] = (int)c.y; d[2] = (int)f.x; d[3] = (int)f.y;
        } else {
            const long long* ps = (const long long*)ei + e0;
            const long long* pd = (const long long*)ei + E + e0;
            for (int k = 0; k < cnt; k++) { s[k] = (int)ps[k]; d[k] = (int)pd[k]; }
        }
    } else {
        if (cnt == 4) {
            int4 a = *(const int4*)((const int*)ei + e0);
            int4 c = *(const int4*)((const int*)ei + E + e0);
            s[0] = a.x; s[1] = a.y; s[2] = a.z; s[3] = a.w;
            d[0] = c.x; d[1] = c.y; d[2] = c.z; d[3] = c.w;
        } else {
            const int* ps = (const int*)ei + e0;
            const int* pd = (const int*)ei + E + e0;
            for (int k = 0; k < cnt; k++) { s[k] = ps[k]; d[k] = pd[k]; }
        }
    }
    for (int k = 0; k < cnt; k++) {
        int src = min(max(s[k], 0), n - 1);
        int dst = min(max(d[k], 0), n - 1);
        int pos = atomicAdd(&g_cursor[dst], 1);
        pos = min(max(pos, 0), EMAX - 1);
        g_srcidx[pos] = src;
    }
}

// ---------------- GEMM layer 1: cp.async 2-stage pipelined tf32 ----------------
// BM=128 BN=128; K in 8 chunks of 16. 8 warps (2m x 4n), warp tile m64 n32.
// Smem holds raw fp32; cvt.rna.tf32 applied at fragment load (registers).
#define CH     16
#define NCH    8
#define G1_AST 20
#define G1_BST 136

__global__ void __launch_bounds__(256) k_gemm1(const float* __restrict__ x,
                                               const float* __restrict__ W, int n) {
    __shared__ float As[2][128 * G1_AST];
    __shared__ float Bs[2][CH * G1_BST];

    const int t = threadIdx.x;
    const int wid = t >> 5, lane = t & 31;
    const int wm = wid & 1, wn = wid >> 1;
    const int m0 = blockIdx.x * 128;

    float acc[4][4][4] = {};

    auto issue = [&](int c, int buf) {
        const int kc = c * CH;
#pragma unroll
        for (int rep = 0; rep < 2; rep++) {
            int i = t + rep * 256;
            int m = i >> 2, seg = i & 3;
            int row = m0 + m;
            bool ok = row < n;
            const float* src = x + ((size_t)(ok ? row : 0) * D_IN + kc + seg * 4);
            uint32_t dst = (uint32_t)__cvta_generic_to_shared(&As[buf][m * G1_AST + seg * 4]);
            asm volatile("cp.async.cg.shared.global [%0], [%1], 16, %2;"
                         :: "r"(dst), "l"(src), "r"(ok ? 16 : 0));
        }
#pragma unroll
        for (int rep = 0; rep < 2; rep++) {
            int i = t + rep * 256;
            int k = i >> 5, seg = i & 31;
            const float* src = W + ((size_t)(kc + k) * D_HID + seg * 4);
            uint32_t dst = (uint32_t)__cvta_generic_to_shared(&Bs[buf][k * G1_BST + seg * 4]);
            asm volatile("cp.async.cg.shared.global [%0], [%1], 16;"
                         :: "r"(dst), "l"(src));
        }
        asm volatile("cp.async.commit_group;");
    };

    issue(0, 0);
    issue(1, 1);

    const int ar = wm * 64 + (lane >> 2);
    const int ac = lane & 3;
    const int bn = wn * 32 + (lane >> 2);

    for (int c = 0; c < NCH; c++) {
        asm volatile("cp.async.wait_group 1;");
        __syncthreads();
        const float* Ab = As[c & 1];
        const float* Bb = Bs[c & 1];
#pragma unroll
        for (int ks = 0; ks < 2; ks++) {
            const int kb = ks * 8;
            uint32_t a[4][4], b[4][2];
#pragma unroll
            for (int mt = 0; mt < 4; mt++) {
                const float* base = Ab + (ar + mt * 16) * G1_AST + kb + ac;
                a[mt][0] = f2tf32(base[0]);
                a[mt][1] = f2tf32(base[8 * G1_AST]);
                a[mt][2] = f2tf32(base[4]);
                a[mt][3] = f2tf32(base[8 * G1_AST + 4]);
            }
#pragma unroll
            for (int nt = 0; nt < 4; nt++) {
                b[nt][0] = f2tf32(Bb[(kb + ac) * G1_BST + bn + nt * 8]);
                b[nt][1] = f2tf32(Bb[(kb + ac + 4) * G1_BST + bn + nt * 8]);
            }
#pragma unroll
            for (int mt = 0; mt < 4; mt++)
#pragma unroll
                for (int nt = 0; nt < 4; nt++) mma_tf32(acc[mt][nt], a[mt], b[nt]);
        }
        __syncthreads();
        if (c + 2 < NCH) issue(c + 2, c & 1);
        else asm volatile("cp.async.commit_group;");
    }

    // epilogue: store RAW result fp16 (dinv deferred to agg1)
    const int rbase = m0 + wm * 64 + (lane >> 2);
    const int cbase = wn * 32 + (lane & 3) * 2;
#pragma unroll
    for (int mt = 0; mt < 4; mt++) {
#pragma unroll
        for (int half = 0; half < 2; half++) {
            int row = rbase + mt * 16 + half * 8;
            if (row < n) {
#pragma unroll
                for (int nt = 0; nt < 4; nt++) {
                    int col = cbase + nt * 8;
                    *(__half2*)&g_g1h[(size_t)row * D_HID + col] =
                        __float22half2_rn(make_float2(acc[mt][nt][2 * half],
                                                      acc[mt][nt][2 * half + 1]));
                }
            }
        }
    }
}

// ---------------- agg1 + L2 activation (deferred dinv) ----------------
__global__ void k_agg1(const float* __restrict__ b1, int n) {
    int gw = (blockIdx.x * blockDim.x + threadIdx.x) >> 5;
    int lane = threadIdx.x & 31;
    int node = gw * 2 + (lane >> 4);
    int lane16 = lane & 15;
    if (node >= n) return;

    const uint4* base = (const uint4*)g_g1h;
    float dv = g_dinv[node];
    float a[8] = {0, 0, 0, 0, 0, 0, 0, 0};
    acc_u4_s(a, base[(size_t)node * 16 + lane16], dv);

    int beg = g_rowstart[node], end = g_rowstart[node + 1];
    int j = beg;
    for (; j + 4 <= end; j += 4) {
        int s0 = g_srcidx[j], s1 = g_srcidx[j + 1], s2 = g_srcidx[j + 2], s3 = g_srcidx[j + 3];
        float v0 = g_dinv[s0], v1 = g_dinv[s1], v2 = g_dinv[s2], v3 = g_dinv[s3];
        uint4 r0 = base[(size_t)s0 * 16 + lane16];
        uint4 r1 = base[(size_t)s1 * 16 + lane16];
        uint4 r2 = base[(size_t)s2 * 16 + lane16];
        uint4 r3 = base[(size_t)s3 * 16 + lane16];
        acc_u4_s(a, r0, v0); acc_u4_s(a, r1, v1); acc_u4_s(a, r2, v2); acc_u4_s(a, r3, v3);
    }
    for (; j < end; j++) {
        int s = g_srcidx[j];
        acc_u4_s(a, base[(size_t)s * 16 + lane16], g_dinv[s]);
    }

    float4 bb0 = *(const float4*)&b1[lane16 * 8];
    float4 bb1 = *(const float4*)&b1[lane16 * 8 + 4];
    float h0 = fmaxf(fmaf(dv, a[0], bb0.x), 0.f), h1 = fmaxf(fmaf(dv, a[1], bb0.y), 0.f);
    float h2 = fmaxf(fmaf(dv, a[2], bb0.z), 0.f), h3 = fmaxf(fmaf(dv, a[3], bb0.w), 0.f);
    float h4 = fmaxf(fmaf(dv, a[4], bb1.x), 0.f), h5 = fmaxf(fmaf(dv, a[5], bb1.y), 0.f);
    float h6 = fmaxf(fmaf(dv, a[6], bb1.z), 0.f), h7 = fmaxf(fmaf(dv, a[7], bb1.w), 0.f);
    uint4 outw;
    *(__half2*)&outw.x = __float22half2_rn(make_float2(h0, h1));
    *(__half2*)&outw.y = __float22half2_rn(make_float2(h2, h3));
    *(__half2*)&outw.z = __float22half2_rn(make_float2(h4, h5));
    *(__half2*)&outw.w = __float22half2_rn(make_float2(h6, h7));
    ((uint4*)g_h1h)[(size_t)node * 16 + lane16] = outw;
}

// ---------------- GEMM layer 2 (tf32, cvt.rna at smem fill) ----------------
#define AS_STRIDE 36
#define BS2_STRIDE 68

__global__ void k_gemm2(const float* __restrict__ W, int n) {
    __shared__ uint32_t As[128 * AS_STRIDE];
    __shared__ uint32_t Bs[32 * BS2_STRIDE];

    const int t = threadIdx.x;
    const int wid = t >> 5, lane = t & 31;
    const int wm = wid & 1, wn = wid >> 1;
    const int m0 = blockIdx.x * 128;

    float acc[4][2][4] = {};

    for (int kc = 0; kc < 128; kc += 32) {
        for (int i = t; i < 1024; i += 256) {
            int m = i >> 3, k4 = (i & 7) * 4;
            int row = m0 + m;
            uint32_t* p = &As[m * AS_STRIDE + k4];
            if (row < n) {
                uint2 raw = *(const uint2*)&g_h1h[(size_t)row * D_HID + kc + k4];
                float2 t0 = __half22float2(*(__half2*)&raw.x);
                float2 t1 = __half22float2(*(__half2*)&raw.y);
                p[0] = f2tf32(t0.x); p[1] = f2tf32(t0.y);
                p[2] = f2tf32(t1.x); p[3] = f2tf32(t1.y);
            } else {
                p[0] = 0u; p[1] = 0u; p[2] = 0u; p[3] = 0u;
            }
        }
        for (int i = t; i < 512; i += 256) {
            int k = i >> 4, n4 = (i & 15) * 4;
            float4 v = *(const float4*)&W[(size_t)(kc + k) * D_OUT + n4];
            uint32_t* p = &Bs[k * BS2_STRIDE + n4];
            p[0] = f2tf32(v.x); p[1] = f2tf32(v.y); p[2] = f2tf32(v.z); p[3] = f2tf32(v.w);
        }
        __syncthreads();

#pragma unroll
        for (int ks = 0; ks < 4; ks++) {
            const int kb = ks * 8;
            uint32_t a[4][4], b[2][2];
            const int ar = wm * 64 + (lane >> 2);
            const int ac = kb + (lane & 3);
#pragma unroll
            for (int mt = 0; mt < 4; mt++) {
                a[mt][0] = As[(ar + mt * 16)     * AS_STRIDE + ac];
                a[mt][1] = As[(ar + mt * 16 + 8) * AS_STRIDE + ac];
                a[mt][2] = As[(ar + mt * 16)     * AS_STRIDE + ac + 4];
                a[mt][3] = As[(ar + mt * 16 + 8) * AS_STRIDE + ac + 4];
            }
            const int bn = wn * 16 + (lane >> 2);
            const int bk = kb + (lane & 3);
#pragma unroll
            for (int nt = 0; nt < 2; nt++) {
                b[nt][0] = Bs[bk       * BS2_STRIDE + bn + nt * 8];
                b[nt][1] = Bs[(bk + 4) * BS2_STRIDE + bn + nt * 8];
            }
#pragma unroll
            for (int mt = 0; mt < 4; mt++)
#pragma unroll
                for (int nt = 0; nt < 2; nt++) mma_tf32(acc[mt][nt], a[mt], b[nt]);
        }
        __syncthreads();
    }

    const int rbase = m0 + wm * 64 + (lane >> 2);
    const int cbase = wn * 16 + (lane & 3) * 2;
#pragma unroll
    for (int mt = 0; mt < 4; mt++) {
#pragma unroll
        for (int half = 0; half < 2; half++) {
            int row = rbase + mt * 16 + half * 8;
            if (row < n) {
                float dv = g_dinv[row];
#pragma unroll
                for (int nt = 0; nt < 2; nt++) {
                    int col = cbase + nt * 8;
                    *(__half2*)&g_g2h[(size_t)row * D_OUT + col] =
                        __float22half2_rn(make_float2(dv * acc[mt][nt][2 * half],
                                                      dv * acc[mt][nt][2 * half + 1]));
                }
            }
        }
    }
}

// ---------------- agg2 + epilogue ----------------
__global__ void k_agg2(const float* __restrict__ b2, float* __restrict__ out, int n) {
    int gw = (blockIdx.x * blockDim.x + threadIdx.x) >> 5;
    int lane = threadIdx.x & 31;
    int node = gw * 4 + (lane >> 3);
    int lane8 = lane & 7;
    if (node >= n) return;

    const uint4* base = (const uint4*)g_g2h;
    float a[8];
    {
        uint4 r = base[(size_t)node * 8 + lane8];
        float2 t;
        t = __half22float2(*(__half2*)&r.x); a[0] = t.x; a[1] = t.y;
        t = __half22float2(*(__half2*)&r.y); a[2] = t.x; a[3] = t.y;
        t = __half22float2(*(__half2*)&r.z); a[4] = t.x; a[5] = t.y;
        t = __half22float2(*(__half2*)&r.w); a[6] = t.x; a[7] = t.y;
    }

    int beg = g_rowstart[node], end = g_rowstart[node + 1];
    int j = beg;
    for (; j + 4 <= end; j += 4) {
        int s0 = g_srcidx[j], s1 = g_srcidx[j + 1], s2 = g_srcidx[j + 2], s3 = g_srcidx[j + 3];
        uint4 r0 = base[(size_t)s0 * 8 + lane8];
        uint4 r1 = base[(size_t)s1 * 8 + lane8];
        uint4 r2 = base[(size_t)s2 * 8 + lane8];
        uint4 r3 = base[(size_t)s3 * 8 + lane8];
        acc_u4(a, r0); acc_u4(a, r1); acc_u4(a, r2); acc_u4(a, r3);
    }
    for (; j < end; j++) {
        uint4 r = base[(size_t)g_srcidx[j] * 8 + lane8];
        acc_u4(a, r);
    }

    float dv = g_dinv[node];
    const float4* b24 = (const float4*)b2;
    float4 bb0 = b24[lane8 * 2], bb1 = b24[lane8 * 2 + 1];
    float4* outp = (float4*)out + (size_t)node * 16 + lane8 * 2;
    outp[0] = make_float4(fmaf(dv, a[0], bb0.x), fmaf(dv, a[1], bb0.y),
                          fmaf(dv, a[2], bb0.z), fmaf(dv, a[3], bb0.w));
    outp[1] = make_float4(fmaf(dv, a[4], bb1.x), fmaf(dv, a[5], bb1.y),
                          fmaf(dv, a[6], bb1.z), fmaf(dv, a[7], bb1.w));
}

// ---------------- launch ----------------
extern "C" void kernel_launch(void* const* d_in, const int* in_sizes, int n_in,
                              void* d_out, int out_size) {
    const float* x  = nullptr;
    const void*  ei = nullptr;
    const float* W1 = nullptr;
    const float* b1 = nullptr;
    const float* W2 = nullptr;
    const float* b2 = nullptr;
    int x_elems = 0, ei_elems = 0;

    int imax = 0, imax2 = -1;
    for (int i = 1; i < n_in; i++) if (in_sizes[i] > in_sizes[imax]) imax = i;
    for (int i = 0; i < n_in; i++) {
        if (i == imax) continue;
        if (imax2 < 0 || in_sizes[i] > in_sizes[imax2]) imax2 = i;
    }
    x  = (const float*)d_in[imax];  x_elems  = in_sizes[imax];
    ei = (const void*)d_in[imax2];  ei_elems = in_sizes[imax2];

    for (int i = 0; i < n_in; i++) {
        if (i == imax || i == imax2) continue;
        int s = in_sizes[i];
        if      (s == D_IN * D_HID)  W1 = (const float*)d_in[i];
        else if (s == D_HID)         b1 = (const float*)d_in[i];
        else if (s == D_HID * D_OUT) W2 = (const float*)d_in[i];
        else if (s == D_OUT)         b2 = (const float*)d_in[i];
    }

    float* out = (float*)d_out;
    const int n = x_elems / D_IN;
    const long long E = (long long)ei_elems / 2;
    const int n1 = n + 1;
    const int nb = (n1 + SCAN_BLK - 1) / SCAN_BLK;
    const long long Q = (E + 3) / 4;
    const int edgeBlocks = (int)((Q + 255) / 256);

    // CSR build
    k_zero_detect<<<(n + 255) / 256, 256>>>((const int*)ei, (long long)ei_elems, n);
    k_count<<<edgeBlocks, 256>>>(ei, E, n);
    k_scan <<<nb, SCAN_BLK>>>(n);
    k_fill <<<edgeBlocks, 256>>>(ei, E, n);

    // layer 1
    k_gemm1<<<(n + 127) / 128, 256>>>(x, W1, n);
    k_agg1 <<<(n + 15) / 16, 256>>>(b1, n);

    // layer 2
    k_gemm2<<<(n + 127) / 128, 256>>>(W2, n);
    k_agg2 <<<(n + 31) / 32, 256>>>(b2, out, n);
}

// round 17
// speedup vs baseline: 1.1631x; 1.0465x over previous
#include <cuda_runtime.h>
#include <cuda_fp16.h>
#include <cstdint>

// GCN 2-layer, CSR-gather + tf32 tensor-core GEMMs (cp.async pipelined) + fp16 gather tensors.
//   dinv[i] = rsqrt(1 + indeg[i])
//   L1: raw1 = x@W1 [fp16, unscaled];  h = relu(dinv*(dinv[i]*raw1[i] + sum dinv[s]*raw1[s]) + b1)
//   L2: g2 = dinv*(h@W2) [fp16];       out = dinv*(g2[i]+sum g2[src]) + b2
// gemm1 (CSR-independent) and CSR-fill are fused with INTERLEAVED block roles
// (blockIdx % r == 0 -> gemm) so both phases co-reside per wave and overlap.
// tf32 conversion uses cvt.rna — raw-bit truncation measured 1.1e-3 (fail).

#define D_IN  128
#define D_HID 128
#define D_OUT 64
#define NMAX  100000
#define EMAX  1600000
#define SCAN_BLK 1024
#define NBLK_MAX 128

// ---- scratch ----
__device__ __align__(16) float g_dinv[NMAX];
__device__ int   g_is64;
__device__ int   g_count[NMAX];
__device__ int   g_rowstart[NMAX + 1];
__device__ int   g_cursor[NMAX];
__device__ volatile unsigned long long g_blkpack[NBLK_MAX];
__device__ int   g_srcidx[EMAX];
__device__ __align__(16) __half g_g1h[(size_t)NMAX * D_HID];  // fp16 raw x@W1
__device__ __align__(16) __half g_h1h[(size_t)NMAX * D_HID];  // fp16 hidden act
__device__ __align__(16) __half g_g2h[(size_t)NMAX * D_OUT];  // fp16 gather tensor L2

// ---------------- tf32 helpers ----------------
__device__ __forceinline__ uint32_t f2tf32(float f) {
    uint32_t u;
    asm("cvt.rna.tf32.f32 %0, %1;" : "=r"(u) : "f"(f));
    return u;
}

__device__ __forceinline__ void mma_tf32(float* d, const uint32_t* a, const uint32_t* b) {
    asm volatile(
        "mma.sync.aligned.m16n8k8.row.col.f32.tf32.tf32.f32 "
        "{%0,%1,%2,%3},{%4,%5,%6,%7},{%8,%9},{%0,%1,%2,%3};"
        : "+f"(d[0]), "+f"(d[1]), "+f"(d[2]), "+f"(d[3])
        : "r"(a[0]), "r"(a[1]), "r"(a[2]), "r"(a[3]), "r"(b[0]), "r"(b[1]));
}

// fp16x8 FMA-accumulate (scaled by s) into fp32x8
__device__ __forceinline__ void acc_u4_s(float* a, uint4 r, float s) {
    float2 t;
    t = __half22float2(*(__half2*)&r.x); a[0] = fmaf(s, t.x, a[0]); a[1] = fmaf(s, t.y, a[1]);
    t = __half22float2(*(__half2*)&r.y); a[2] = fmaf(s, t.x, a[2]); a[3] = fmaf(s, t.y, a[3]);
    t = __half22float2(*(__half2*)&r.z); a[4] = fmaf(s, t.x, a[4]); a[5] = fmaf(s, t.y, a[5]);
    t = __half22float2(*(__half2*)&r.w); a[6] = fmaf(s, t.x, a[6]); a[7] = fmaf(s, t.y, a[7]);
}

// fp16x8 accumulate into fp32x8
__device__ __forceinline__ void acc_u4(float* a, uint4 r) {
    float2 t;
    t = __half22float2(*(__half2*)&r.x); a[0] += t.x; a[1] += t.y;
    t = __half22float2(*(__half2*)&r.y); a[2] += t.x; a[3] += t.y;
    t = __half22float2(*(__half2*)&r.z); a[4] += t.x; a[5] += t.y;
    t = __half22float2(*(__half2*)&r.w); a[6] += t.x; a[7] += t.y;
}

// ---------------- zero + dtype detect ----------------
__global__ void k_zero_detect(const int* __restrict__ w, long long words32, int n) {
    int i = blockIdx.x * blockDim.x + threadIdx.x;
    if (i < n) g_count[i] = 0;
    if (i < NBLK_MAX) g_blkpack[i] = 0ull;
    if (blockIdx.x == 0) {
        __shared__ int nzflag;
        if (threadIdx.x == 0) nzflag = 0;
        __syncthreads();
        long long limit = words32 < 8192 ? words32 : 8192;
        for (long long k = 1 + 2 * (long long)threadIdx.x; k < limit; k += 2 * blockDim.x)
            if (w[k] != 0) nzflag = 1;
        __syncthreads();
        if (threadIdx.x == 0) g_is64 = (nzflag == 0) ? 1 : 0;
    }
}

// ---------------- count (4 edges/thread) ----------------
__global__ void k_count(const void* __restrict__ ei, long long E, int n) {
    long long q = (long long)blockIdx.x * blockDim.x + threadIdx.x;
    long long e0 = q * 4;
    if (e0 >= E) return;
    int d[4];
    int cnt = (int)((E - e0) < 4 ? (E - e0) : 4);
    if (g_is64) {
        if (cnt == 4) {
            const longlong2* p = (const longlong2*)((const long long*)ei + E + e0);
            longlong2 a = p[0], b = p[1];
            d[0] = (int)a.x; d[1] = (int)a.y; d[2] = (int)b.x; d[3] = (int)b.y;
        } else {
            const long long* s = (const long long*)ei + E + e0;
            for (int k = 0; k < cnt; k++) d[k] = (int)s[k];
        }
    } else {
        if (cnt == 4) {
            int4 a = *(const int4*)((const int*)ei + E + e0);
            d[0] = a.x; d[1] = a.y; d[2] = a.z; d[3] = a.w;
        } else {
            const int* s = (const int*)ei + E + e0;
            for (int k = 0; k < cnt; k++) d[k] = s[k];
        }
    }
    for (int k = 0; k < cnt; k++) {
        int dst = min(max(d[k], 0), n - 1);
        atomicAdd(&g_count[dst], 1);
    }
}

// ---------------- decoupled-lookback scan ----------------
__global__ void k_scan(int n) {
    __shared__ int sm[SCAN_BLK];
    __shared__ int s_prev;
    const int b = blockIdx.x;
    const int tid = threadIdx.x;
    const int gid = b * SCAN_BLK + tid;
    const int n1 = n + 1;

    int v = (gid < n) ? g_count[gid] : 0;
    sm[tid] = v;
    __syncthreads();
    for (int off = 1; off < SCAN_BLK; off <<= 1) {
        int t = (tid >= off) ? sm[tid - off] : 0;
        __syncthreads();
        sm[tid] += t;
        __syncthreads();
    }
    int incl = sm[tid];

    if (tid == SCAN_BLK - 1)
        g_blkpack[b] = ((unsigned long long)(unsigned)incl << 32) | 1ull;

    if (tid == 0) s_prev = 0;
    __syncthreads();
    int part = 0;
    for (int j = tid; j < b; j += SCAN_BLK) {
        unsigned long long w;
        do { w = g_blkpack[j]; } while (w == 0ull);
        part += (int)(w >> 32);
    }
    if (part) atomicAdd(&s_prev, part);
    __syncthreads();
    int prev = s_prev;

    int excl = prev + incl - v;
    if (gid < n1) g_rowstart[gid] = excl;
    if (gid < n) {
        g_cursor[gid] = excl;
        g_dinv[gid] = rsqrtf((float)v + 1.0f);
    }
}

// ---------------- FUSED gemm1 || fill, interleaved block roles ----------------
// gemm: BM=128 BN=128, K in 8 chunks of 16, cp.async 2-stage.
// fill: 4 edges/thread.
// role: blockIdx % r == 0 (and gemmId < G) -> gemm; else fill.
#define CH     16
#define NCH    8
#define G1_AST 20
#define G1_BST 136

__global__ void __launch_bounds__(256) k_gemm1_fill(
    const float* __restrict__ x, const float* __restrict__ W,
    const void* __restrict__ ei, long long E, int n, int G, int r) {
    __shared__ float As[2][128 * G1_AST];
    __shared__ float Bs[2][CH * G1_BST];

    const int idx = blockIdx.x;
    const bool is_gemm = (idx % r == 0) && (idx / r < G);

    if (!is_gemm) {
        // ---- fill branch ----
        // fillId = idx - (#gemm blocks with index < idx)
        int ng = (idx + r - 1) / r;
        if (ng > G) ng = G;
        long long q = (long long)(idx - ng) * blockDim.x + threadIdx.x;
        long long e0 = q * 4;
        if (e0 >= E) return;
        int s[4], d[4];
        int cnt = (int)((E - e0) < 4 ? (E - e0) : 4);
        if (g_is64) {
            if (cnt == 4) {
                const longlong2* ps = (const longlong2*)((const long long*)ei + e0);
                const longlong2* pd = (const longlong2*)((const long long*)ei + E + e0);
                longlong2 a = ps[0], b = ps[1], c = pd[0], f = pd[1];
                s[0] = (int)a.x; s[1] = (int)a.y; s[2] = (int)b.x; s[3] = (int)b.y;
                d[0] = (int)c.x; d[1] = (int)c.y; d[2] = (int)f.x; d[3] = (int)f.y;
            } else {
                const long long* ps = (const long long*)ei + e0;
                const long long* pd = (const long long*)ei + E + e0;
                for (int k = 0; k < cnt; k++) { s[k] = (int)ps[k]; d[k] = (int)pd[k]; }
            }
        } else {
            if (cnt == 4) {
                int4 a = *(const int4*)((const int*)ei + e0);
                int4 c = *(const int4*)((const int*)ei + E + e0);
                s[0] = a.x; s[1] = a.y; s[2] = a.z; s[3] = a.w;
                d[0] = c.x; d[1] = c.y; d[2] = c.z; d[3] = c.w;
            } else {
                const int* ps = (const int*)ei + e0;
                const int* pd = (const int*)ei + E + e0;
                for (int k = 0; k < cnt; k++) { s[k] = ps[k]; d[k] = pd[k]; }
            }
        }
        for (int k = 0; k < cnt; k++) {
            int src = min(max(s[k], 0), n - 1);
            int dst = min(max(d[k], 0), n - 1);
            int pos = atomicAdd(&g_cursor[dst], 1);
            pos = min(max(pos, 0), EMAX - 1);
            g_srcidx[pos] = src;
        }
        return;
    }

    // ---- gemm branch ----
    const int t = threadIdx.x;
    const int wid = t >> 5, lane = t & 31;
    const int wm = wid & 1, wn = wid >> 1;
    const int m0 = (idx / r) * 128;

    float acc[4][4][4] = {};

    auto issue = [&](int c, int buf) {
        const int kc = c * CH;
#pragma unroll
        for (int rep = 0; rep < 2; rep++) {
            int i = t + rep * 256;
            int m = i >> 2, seg = i & 3;
            int row = m0 + m;
            bool ok = row < n;
            const float* src = x + ((size_t)(ok ? row : 0) * D_IN + kc + seg * 4);
            uint32_t dst = (uint32_t)__cvta_generic_to_shared(&As[buf][m * G1_AST + seg * 4]);
            asm volatile("cp.async.cg.shared.global [%0], [%1], 16, %2;"
                         :: "r"(dst), "l"(src), "r"(ok ? 16 : 0));
        }
#pragma unroll
        for (int rep = 0; rep < 2; rep++) {
            int i = t + rep * 256;
            int k = i >> 5, seg = i & 31;
            const float* src = W + ((size_t)(kc + k) * D_HID + seg * 4);
            uint32_t dst = (uint32_t)__cvta_generic_to_shared(&Bs[buf][k * G1_BST + seg * 4]);
            asm volatile("cp.async.cg.shared.global [%0], [%1], 16;"
                         :: "r"(dst), "l"(src));
        }
        asm volatile("cp.async.commit_group;");
    };

    issue(0, 0);
    issue(1, 1);

    const int ar = wm * 64 + (lane >> 2);
    const int ac = lane & 3;
    const int bn = wn * 32 + (lane >> 2);

    for (int c = 0; c < NCH; c++) {
        asm volatile("cp.async.wait_group 1;");
        __syncthreads();
        const float* Ab = As[c & 1];
        const float* Bb = Bs[c & 1];
#pragma unroll
        for (int ks = 0; ks < 2; ks++) {
            const int kb = ks * 8;
            uint32_t a[4][4], b[4][2];
#pragma unroll
            for (int mt = 0; mt < 4; mt++) {
                const float* base = Ab + (ar + mt * 16) * G1_AST + kb + ac;
                a[mt][0] = f2tf32(base[0]);
                a[mt][1] = f2tf32(base[8 * G1_AST]);
                a[mt][2] = f2tf32(base[4]);
                a[mt][3] = f2tf32(base[8 * G1_AST + 4]);
            }
#pragma unroll
            for (int nt = 0; nt < 4; nt++) {
                b[nt][0] = f2tf32(Bb[(kb + ac) * G1_BST + bn + nt * 8]);
                b[nt][1] = f2tf32(Bb[(kb + ac + 4) * G1_BST + bn + nt * 8]);
            }
#pragma unroll
            for (int mt = 0; mt < 4; mt++)
#pragma unroll
                for (int nt = 0; nt < 4; nt++) mma_tf32(acc[mt][nt], a[mt], b[nt]);
        }
        __syncthreads();
        if (c + 2 < NCH) issue(c + 2, c & 1);
        else asm volatile("cp.async.commit_group;");
    }

    // epilogue: store RAW result fp16 (dinv deferred to agg1)
    const int rbase = m0 + wm * 64 + (lane >> 2);
    const int cbase = wn * 32 + (lane & 3) * 2;
#pragma unroll
    for (int mt = 0; mt < 4; mt++) {
#pragma unroll
        for (int half = 0; half < 2; half++) {
            int row = rbase + mt * 16 + half * 8;
            if (row < n) {
#pragma unroll
                for (int nt = 0; nt < 4; nt++) {
                    int col = cbase + nt * 8;
                    *(__half2*)&g_g1h[(size_t)row * D_HID + col] =
                        __float22half2_rn(make_float2(acc[mt][nt][2 * half],
                                                      acc[mt][nt][2 * half + 1]));
                }
            }
        }
    }
}

// ---------------- agg1 + L2 activation (deferred dinv) ----------------
__global__ void k_agg1(const float* __restrict__ b1, int n) {
    int gw = (blockIdx.x * blockDim.x + threadIdx.x) >> 5;
    int lane = threadIdx.x & 31;
    int node = gw * 2 + (lane >> 4);
    int lane16 = lane & 15;
    if (node >= n) return;

    const uint4* base = (const uint4*)g_g1h;
    float dv = g_dinv[node];
    float a[8] = {0, 0, 0, 0, 0, 0, 0, 0};
    acc_u4_s(a, base[(size_t)node * 16 + lane16], dv);

    int beg = g_rowstart[node], end = g_rowstart[node + 1];
    int j = beg;
    for (; j + 4 <= end; j += 4) {
        int s0 = g_srcidx[j], s1 = g_srcidx[j + 1], s2 = g_srcidx[j + 2], s3 = g_srcidx[j + 3];
        float v0 = g_dinv[s0], v1 = g_dinv[s1], v2 = g_dinv[s2], v3 = g_dinv[s3];
        uint4 r0 = base[(size_t)s0 * 16 + lane16];
        uint4 r1 = base[(size_t)s1 * 16 + lane16];
        uint4 r2 = base[(size_t)s2 * 16 + lane16];
        uint4 r3 = base[(size_t)s3 * 16 + lane16];
        acc_u4_s(a, r0, v0); acc_u4_s(a, r1, v1); acc_u4_s(a, r2, v2); acc_u4_s(a, r3, v3);
    }
    for (; j < end; j++) {
        int s = g_srcidx[j];
        acc_u4_s(a, base[(size_t)s * 16 + lane16], g_dinv[s]);
    }

    float4 bb0 = *(const float4*)&b1[lane16 * 8];
    float4 bb1 = *(const float4*)&b1[lane16 * 8 + 4];
    float h0 = fmaxf(fmaf(dv, a[0], bb0.x), 0.f), h1 = fmaxf(fmaf(dv, a[1], bb0.y), 0.f);
    float h2 = fmaxf(fmaf(dv, a[2], bb0.z), 0.f), h3 = fmaxf(fmaf(dv, a[3], bb0.w), 0.f);
    float h4 = fmaxf(fmaf(dv, a[4], bb1.x), 0.f), h5 = fmaxf(fmaf(dv, a[5], bb1.y), 0.f);
    float h6 = fmaxf(fmaf(dv, a[6], bb1.z), 0.f), h7 = fmaxf(fmaf(dv, a[7], bb1.w), 0.f);
    uint4 outw;
    *(__half2*)&outw.x = __float22half2_rn(make_float2(h0, h1));
    *(__half2*)&outw.y = __float22half2_rn(make_float2(h2, h3));
    *(__half2*)&outw.z = __float22half2_rn(make_float2(h4, h5));
    *(__half2*)&outw.w = __float22half2_rn(make_float2(h6, h7));
    ((uint4*)g_h1h)[(size_t)node * 16 + lane16] = outw;
}

// ---------------- GEMM layer 2 (tf32, cvt.rna at smem fill) ----------------
#define AS_STRIDE 36
#define BS2_STRIDE 68

__global__ void k_gemm2(const float* __restrict__ W, int n) {
    __shared__ uint32_t As[128 * AS_STRIDE];
    __shared__ uint32_t Bs[32 * BS2_STRIDE];

    const int t = threadIdx.x;
    const int wid = t >> 5, lane = t & 31;
    const int wm = wid & 1, wn = wid >> 1;
    const int m0 = blockIdx.x * 128;

    float acc[4][2][4] = {};

    for (int kc = 0; kc < 128; kc += 32) {
        for (int i = t; i < 1024; i += 256) {
            int m = i >> 3, k4 = (i & 7) * 4;
            int row = m0 + m;
            uint32_t* p = &As[m * AS_STRIDE + k4];
            if (row < n) {
                uint2 raw = *(const uint2*)&g_h1h[(size_t)row * D_HID + kc + k4];
                float2 t0 = __half22float2(*(__half2*)&raw.x);
                float2 t1 = __half22float2(*(__half2*)&raw.y);
                p[0] = f2tf32(t0.x); p[1] = f2tf32(t0.y);
                p[2] = f2tf32(t1.x); p[3] = f2tf32(t1.y);
            } else {
                p[0] = 0u; p[1] = 0u; p[2] = 0u; p[3] = 0u;
            }
        }
        for (int i = t; i < 512; i += 256) {
            int k = i >> 4, n4 = (i & 15) * 4;
            float4 v = *(const float4*)&W[(size_t)(kc + k) * D_OUT + n4];
            uint32_t* p = &Bs[k * BS2_STRIDE + n4];
            p[0] = f2tf32(v.x); p[1] = f2tf32(v.y); p[2] = f2tf32(v.z); p[3] = f2tf32(v.w);
        }
        __syncthreads();

#pragma unroll
        for (int ks = 0; ks < 4; ks++) {
            const int kb = ks * 8;
            uint32_t a[4][4], b[2][2];
            const int ar = wm * 64 + (lane >> 2);
            const int ac = kb + (lane & 3);
#pragma unroll
            for (int mt = 0; mt < 4; mt++) {
                a[mt][0] = As[(ar + mt * 16)     * AS_STRIDE + ac];
                a[mt][1] = As[(ar + mt * 16 + 8) * AS_STRIDE + ac];
                a[mt][2] = As[(ar + mt * 16)     * AS_STRIDE + ac + 4];
                a[mt][3] = As[(ar + mt * 16 + 8) * AS_STRIDE + ac + 4];
            }
            const int bn = wn * 16 + (lane >> 2);
            const int bk = kb + (lane & 3);
#pragma unroll
            for (int nt = 0; nt < 2; nt++) {
                b[nt][0] = Bs[bk       * BS2_STRIDE + bn + nt * 8];
                b[nt][1] = Bs[(bk + 4) * BS2_STRIDE + bn + nt * 8];
            }
#pragma unroll
            for (int mt = 0; mt < 4; mt++)
#pragma unroll
                for (int nt = 0; nt < 2; nt++) mma_tf32(acc[mt][nt], a[mt], b[nt]);
        }
        __syncthreads();
    }

    const int rbase = m0 + wm * 64 + (lane >> 2);
    const int cbase = wn * 16 + (lane & 3) * 2;
#pragma unroll
    for (int mt = 0; mt < 4; mt++) {
#pragma unroll
        for (int half = 0; half < 2; half++) {
            int row = rbase + mt * 16 + half * 8;
            if (row < n) {
                float dv = g_dinv[row];
#pragma unroll
                for (int nt = 0; nt < 2; nt++) {
                    int col = cbase + nt * 8;
                    *(__half2*)&g_g2h[(size_t)row * D_OUT + col] =
                        __float22half2_rn(make_float2(dv * acc[mt][nt][2 * half],
                                                      dv * acc[mt][nt][2 * half + 1]));
                }
            }
        }
    }
}

// ---------------- agg2 + epilogue ----------------
__global__ void k_agg2(const float* __restrict__ b2, float* __restrict__ out, int n) {
    int gw = (blockIdx.x * blockDim.x + threadIdx.x) >> 5;
    int lane = threadIdx.x & 31;
    int node = gw * 4 + (lane >> 3);
    int lane8 = lane & 7;
    if (node >= n) return;

    const uint4* base = (const uint4*)g_g2h;
    float a[8];
    {
        uint4 r = base[(size_t)node * 8 + lane8];
        float2 t;
        t = __half22float2(*(__half2*)&r.x); a[0] = t.x; a[1] = t.y;
        t = __half22float2(*(__half2*)&r.y); a[2] = t.x; a[3] = t.y;
        t = __half22float2(*(__half2*)&r.z); a[4] = t.x; a[5] = t.y;
        t = __half22float2(*(__half2*)&r.w); a[6] = t.x; a[7] = t.y;
    }

    int beg = g_rowstart[node], end = g_rowstart[node + 1];
    int j = beg;
    for (; j + 4 <= end; j += 4) {
        int s0 = g_srcidx[j], s1 = g_srcidx[j + 1], s2 = g_srcidx[j + 2], s3 = g_srcidx[j + 3];
        uint4 r0 = base[(size_t)s0 * 8 + lane8];
        uint4 r1 = base[(size_t)s1 * 8 + lane8];
        uint4 r2 = base[(size_t)s2 * 8 + lane8];
        uint4 r3 = base[(size_t)s3 * 8 + lane8];
        acc_u4(a, r0); acc_u4(a, r1); acc_u4(a, r2); acc_u4(a, r3);
    }
    for (; j < end; j++) {
        uint4 r = base[(size_t)g_srcidx[j] * 8 + lane8];
        acc_u4(a, r);
    }

    float dv = g_dinv[node];
    const float4* b24 = (const float4*)b2;
    float4 bb0 = b24[lane8 * 2], bb1 = b24[lane8 * 2 + 1];
    float4* outp = (float4*)out + (size_t)node * 16 + lane8 * 2;
    outp[0] = make_float4(fmaf(dv, a[0], bb0.x), fmaf(dv, a[1], bb0.y),
                          fmaf(dv, a[2], bb0.z), fmaf(dv, a[3], bb0.w));
    outp[1] = make_float4(fmaf(dv, a[4], bb1.x), fmaf(dv, a[5], bb1.y),
                          fmaf(dv, a[6], bb1.z), fmaf(dv, a[7], bb1.w));
}

// ---------------- launch ----------------
extern "C" void kernel_launch(void* const* d_in, const int* in_sizes, int n_in,
                              void* d_out, int out_size) {
    const float* x  = nullptr;
    const void*  ei = nullptr;
    const float* W1 = nullptr;
    const float* b1 = nullptr;
    const float* W2 = nullptr;
    const float* b2 = nullptr;
    int x_elems = 0, ei_elems = 0;

    int imax = 0, imax2 = -1;
    for (int i = 1; i < n_in; i++) if (in_sizes[i] > in_sizes[imax]) imax = i;
    for (int i = 0; i < n_in; i++) {
        if (i == imax) continue;
        if (imax2 < 0 || in_sizes[i] > in_sizes[imax2]) imax2 = i;
    }
    x  = (const float*)d_in[imax];  x_elems  = in_sizes[imax];
    ei = (const void*)d_in[imax2]; ei_elems = in_sizes[imax2];

    for (int i = 0; i < n_in; i++) {
        if (i == imax || i == imax2) continue;
        int s = in_sizes[i];
        if      (s == D_IN * D_HID)  W1 = (const float*)d_in[i];
        else if (s == D_HID)         b1 = (const float*)d_in[i];
        else if (s == D_HID * D_OUT) W2 = (const float*)d_in[i];
        else if (s == D_OUT)         b2 = (const float*)d_in[i];
    }

    float* out = (float*)d_out;
    const int n = x_elems / D_IN;
    const long long E = (long long)ei_elems / 2;
    const int n1 = n + 1;
    const int nb = (n1 + SCAN_BLK - 1) / SCAN_BLK;
    const long long Q = (E + 3) / 4;
    const int fillBlocks = (int)((Q + 255) / 256);
    const int gemmBlocks = (n + 127) / 128;
    const int totBlocks  = gemmBlocks + fillBlocks;
    int r = totBlocks / gemmBlocks;          // interleave factor (>=1)
    if (r < 1) r = 1;

    // CSR count + scan (gemm1 does not depend on these)
    k_zero_detect<<<(n + 255) / 256, 256>>>((const int*)ei, (long long)ei_elems, n);
    k_count<<<fillBlocks, 256>>>(ei, E, n);
    k_scan <<<nb, SCAN_BLK>>>(n);

    // fused + interleaved: gemm1 || fill
    k_gemm1_fill<<<totBlocks, 256>>>(x, W1, ei, E, n, gemmBlocks, r);

    // layer 1 aggregation (+ReLU/bias)
    k_agg1 <<<(n + 15) / 16, 256>>>(b1, n);

    // layer 2
    k_gemm2<<<gemmBlocks, 256>>>(W2, n);
    k_agg2 <<<(n + 31) / 32, 256>>>(b2, out, n);
}